// round 2
// baseline (speedup 1.0000x reference)
#include <cuda_runtime.h>
#include <cstdint>

#define NTOK 65536
#define D 128
#define MT 64
#define MAXT 1032
#define SM_X 0
#define SM_W 8448
#define SM_P 8448
#define SM_Q 16640
#define SM_B 43264
#define SM_T 43776
#define SM_FLOATS 43840
#define WSTG 17408
#define WG 4352

__device__ int g_cnt[9];
__device__ int g_fmt64;
__device__ int g_ntiles;
__device__ int g_tok[9 * NTOK];
__device__ int g_te[MAXT], g_ts[MAXT], g_tn[MAXT];
__device__ float g_Wr[2 * 4 * 9 * 128 * 128];

__device__ __forceinline__ uint32_t f2tf(float f) {
    uint32_t r; asm("cvt.rna.tf32.f32 %0,%1;" : "=r"(r) : "f"(f)); return r;
}
__device__ __forceinline__ float ex2f(float x) {
    float r; asm("ex2.approx.f32 %0,%1;" : "=f"(r) : "f"(x)); return r;
}
__device__ __forceinline__ float rcpf(float x) {
    float r; asm("rcp.approx.f32 %0,%1;" : "=f"(r) : "f"(x)); return r;
}
__device__ __forceinline__ float sigf(float v) {
    return rcpf(1.f + ex2f(-1.4426950408889634f * v));
}
__device__ __forceinline__ float tanhfast(float v) {
    return 2.f * rcpf(1.f + ex2f(-2.8853900817779268f * v)) - 1.f;
}
__device__ __forceinline__ void mma8(float* c, const uint32_t* a, uint32_t b0, uint32_t b1) {
    asm volatile(
        "mma.sync.aligned.m16n8k8.row.col.f32.tf32.tf32.f32 "
        "{%0,%1,%2,%3},{%4,%5,%6,%7},{%8,%9},{%0,%1,%2,%3};"
        : "+f"(c[0]), "+f"(c[1]), "+f"(c[2]), "+f"(c[3])
        : "r"(a[0]), "r"(a[1]), "r"(a[2]), "r"(a[3]), "r"(b0), "r"(b1));
}
__device__ __forceinline__ uint32_t sptr(const void* p) {
    return (uint32_t)__cvta_generic_to_shared(p);
}
__device__ __forceinline__ void cpa16(uint32_t dst, const void* src) {
    asm volatile("cp.async.cg.shared.global [%0],[%1],16;" :: "r"(dst), "l"(src));
}

__global__ void k_prep(const int* __restrict__ pos) {
    int tid = threadIdx.x;
    if (tid < 9) g_cnt[tid] = 0;
    if (tid == 0) g_fmt64 = 1;
    __syncthreads();
    int bad = 0;
    for (int i = tid; i < 8192; i += 256) bad |= (pos[2 * i + 1] != 0);
    if (__syncthreads_or(bad)) { if (tid == 0) g_fmt64 = 0; }
}

__global__ void k_round(const float4* __restrict__ W) {
    int i = blockIdx.x * 256 + threadIdx.x;
    float4 v = W[i];
    uint4 o;
    o.x = f2tf(v.x); o.y = f2tf(v.y); o.z = f2tf(v.z); o.w = f2tf(v.w);
    ((uint4*)g_Wr)[i] = o;
}

__global__ void k_assign(const int* __restrict__ pos) {
    int t = blockIdx.x * 256 + threadIdx.x;
    int p = g_fmt64 ? pos[2 * t] : pos[t];
    int e = p; if (e > 8) e = 8; if (e < 0) e = 0;
    int s = atomicAdd(&g_cnt[e], 1);
    g_tok[e * NTOK + s] = t;
}

__global__ void k_tiles() {
    if (threadIdx.x) return;
    int nt = 0;
    for (int e = 0; e < 9; e++) {
        int c = g_cnt[e];
        for (int s = 0; s < c; s += MT) {
            g_te[nt] = e; g_ts[nt] = s;
            g_tn[nt] = (c - s < MT) ? (c - s) : MT;
            nt++;
        }
    }
    g_ntiles = nt;
}

// Per (mt,nt,j) fragment: row/col per PTX m16n8k8 layout; g*D picks this warp's bias row.
#define FRAG_LOOP(BODY) \
    _Pragma("unroll") for (int mt = 0; mt < 2; mt++) \
    _Pragma("unroll") for (int nt = 0; nt < 16; nt++) \
    _Pragma("unroll") for (int j = 0; j < 4; j++) { \
        int r = h * 32 + mt * 16 + grp + ((j >> 1) << 3); \
        int c = nt * 8 + tig * 2 + (j & 1); \
        float v = acc[mt][nt][j] + sm[SM_B + g * D + c]; \
        (void)v; BODY }

__global__ void __launch_bounds__(256, 1)
k_main(const float* __restrict__ xin, const float* __restrict__ bs, float* __restrict__ out) {
    extern __shared__ float sm[];
    int bid = blockIdx.x;
    if (bid >= g_ntiles) return;
    int e = g_te[bid], s0 = g_ts[bid], nr = g_tn[bid];
    int tid = threadIdx.x, lane = tid & 31, w = tid >> 5;
    int g = w >> 1, h = w & 1, tig = lane & 3, grp = lane >> 2;

    int* stok = (int*)(sm + SM_T);
    if (tid < MT) stok[tid] = (tid < nr) ? g_tok[e * NTOK + s0 + tid] : -1;
    __syncthreads();
    for (int i = tid; i < MT * D; i += 256) {
        int r = i >> 7, c = i & 127;
        int t = stok[r];
        sm[SM_X + r * 132 + c] = (t >= 0) ? xin[(size_t)t * D + c] : 0.f;
    }

    for (int l = 0; l < 2; l++) {
        for (int i = tid; i < 512; i += 256)
            sm[SM_B + i] = bs[((l * 4 + (i >> 7)) * 9 + e) * D + (i & 127)];
        __syncthreads();

        const float* wbase = g_Wr + ((size_t)(l * 4) * 9 + e) * 16384;
        auto copy_chunk = [&](int kc, int stg) {
            for (int i = tid; i < 4096; i += 256) {
                int gg = i >> 10, rem = i & 1023, kr = rem >> 5, c4 = rem & 31;
                const float* src = wbase + (size_t)gg * 9 * 16384 + (kc * 32 + kr) * 128 + c4 * 4;
                cpa16(sptr(sm + SM_W + stg * WSTG + gg * WG + kr * 136 + c4 * 4), src);
            }
            asm volatile("cp.async.commit_group;");
        };

        copy_chunk(0, 0);
        copy_chunk(1, 1);
        float acc[2][16][4];
        #pragma unroll
        for (int mt = 0; mt < 2; mt++)
            #pragma unroll
            for (int nt = 0; nt < 16; nt++)
                #pragma unroll
                for (int j = 0; j < 4; j++) acc[mt][nt][j] = 0.f;

        for (int kc = 0; kc < 4; kc++) {
            if (kc == 3) asm volatile("cp.async.wait_group 0;");
            else         asm volatile("cp.async.wait_group 1;");
            __syncthreads();
            int stg = kc & 1;
            const uint32_t* swu = (const uint32_t*)(sm + SM_W + stg * WSTG + g * WG);
            #pragma unroll
            for (int ks = 0; ks < 4; ks++) {
                int kr = ks * 8 + tig;
                uint32_t a[2][4];
                #pragma unroll
                for (int mt = 0; mt < 2; mt++) {
                    int r0 = h * 32 + mt * 16 + grp;
                    int ck = kc * 32 + kr;
                    a[mt][0] = f2tf(sm[SM_X + r0 * 132 + ck]);
                    a[mt][1] = f2tf(sm[SM_X + (r0 + 8) * 132 + ck]);
                    a[mt][2] = f2tf(sm[SM_X + r0 * 132 + ck + 4]);
                    a[mt][3] = f2tf(sm[SM_X + (r0 + 8) * 132 + ck + 4]);
                }
                #pragma unroll
                for (int nt = 0; nt < 16; nt++) {
                    uint32_t b0 = swu[kr * 136 + nt * 8 + grp];
                    uint32_t b1 = swu[(kr + 4) * 136 + nt * 8 + grp];
                    mma8(acc[0][nt], a[0], b0, b1);
                    mma8(acc[1][nt], a[1], b0, b1);
                }
            }
            __syncthreads();
            if (kc < 2) copy_chunk(kc + 2, stg);
        }

        float* P = sm + SM_P;
        float* Q = sm + SM_Q;
        if (g == 0) {
            FRAG_LOOP( P[r * D + c] = sm[SM_X + r * 132 + c] * sigf(v); )
        } else if (g == 1) {
            FRAG_LOOP( Q[r * D + c] = tanhfast(v); )
        }
        __syncthreads();
        if (g == 2) {
            FRAG_LOOP( P[r * D + c] += Q[r * D + c] * sigf(v); )
        }
        __syncthreads();
        if (g == 3) {
            FRAG_LOOP( P[r * D + c] = tanhfast(P[r * D + c]) * sigf(v); )
        }
        __syncthreads();
        if (l == 0) {
            for (int i = tid; i < MT * D; i += 256)
                sm[SM_X + (i >> 7) * 132 + (i & 127)] = P[i];
        } else {
            for (int i = tid; i < MT * D; i += 256) {
                int r = i >> 7;
                int t = stok[r];
                if (t >= 0) out[(size_t)t * D + (i & 127)] = P[i];
            }
        }
        __syncthreads();
    }
}

extern "C" void kernel_launch(void* const* d_in, const int* in_sizes, int n_in,
                              void* d_out, int out_size) {
    const int* pos = (const int*)d_in[0];
    const float* x = (const float*)d_in[1];
    const float4* W = (const float4*)d_in[2];
    const float* b = (const float*)d_in[3];
    float* out = (float*)d_out;
    (void)in_sizes; (void)n_in; (void)out_size;
    cudaFuncSetAttribute(k_main, cudaFuncAttributeMaxDynamicSharedMemorySize, SM_FLOATS * 4);
    k_prep<<<1, 256>>>(pos);
    k_round<<<1152, 256>>>(W);
    k_assign<<<256, 256>>>(pos);
    k_tiles<<<1, 32>>>();
    k_main<<<MAXT, 256, SM_FLOATS * 4>>>(x, b, out);
}

// round 4
// speedup vs baseline: 2.0235x; 2.0235x over previous
#include <cuda_runtime.h>
#include <cstdint>

#define NTOK 65536
#define MT 64
#define MAXTILE 1040

// byte offsets in dynamic smem
#define SM_X    0         // 64*132*4 = 33792 B fp32 X tile (pad 132)
#define SM_B    33792     // 2 x 65536 B : B double buffer (fragment-ordered)
#define SM_BIAS 164864    // 512 floats
#define SM_TOK  166912    // 64 ints
#define SMEM_MAIN 167168

__device__ int g_cnt[9];
__device__ int g_fmt64;
__device__ int g_ntiles;
__device__ int g_tok[9 * NTOK];
__device__ int g_te[MAXTILE], g_ts[MAXTILE], g_tn[MAXTILE];
// fragment-ordered tf32 weights: [l][e] blocks of 65536 words
// word idx = kc*16384 + ks_in*4096 + gate*1024 + nh*512 + ntp*128 + lane*4 + q
__device__ __align__(16) uint32_t g_Wf[18 * 65536];

__device__ __forceinline__ uint32_t f2tf(float f) {
    uint32_t r; asm("cvt.rna.tf32.f32 %0,%1;" : "=r"(r) : "f"(f)); return r;
}
__device__ __forceinline__ float ex2f(float x) {
    float r; asm("ex2.approx.f32 %0,%1;" : "=f"(r) : "f"(x)); return r;
}
__device__ __forceinline__ float rcpf(float x) {
    float r; asm("rcp.approx.f32 %0,%1;" : "=f"(r) : "f"(x)); return r;
}
__device__ __forceinline__ float sigf(float v) {
    return rcpf(1.f + ex2f(-1.4426950408889634f * v));
}
__device__ __forceinline__ float tanhfast(float v) {
    return 2.f * rcpf(1.f + ex2f(-2.8853900817779268f * v)) - 1.f;
}
__device__ __forceinline__ void mma8(float* c, const uint32_t* a, uint32_t b0, uint32_t b1) {
    asm volatile(
        "mma.sync.aligned.m16n8k8.row.col.f32.tf32.tf32.f32 "
        "{%0,%1,%2,%3},{%4,%5,%6,%7},{%8,%9},{%0,%1,%2,%3};"
        : "+f"(c[0]), "+f"(c[1]), "+f"(c[2]), "+f"(c[3])
        : "r"(a[0]), "r"(a[1]), "r"(a[2]), "r"(a[3]), "r"(b0), "r"(b1));
}
__device__ __forceinline__ uint32_t sptr(const void* p) {
    return (uint32_t)__cvta_generic_to_shared(p);
}
__device__ __forceinline__ void cpa16(uint32_t dst, const void* src) {
    asm volatile("cp.async.cg.shared.global [%0],[%1],16;" :: "r"(dst), "l"(src));
}

// ---------------- prep ----------------
__global__ void k_prep(const int* __restrict__ pos) {
    int tid = threadIdx.x;
    if (tid < 9) g_cnt[tid] = 0;
    int bad = 0;
    for (int i = tid; i < 8192; i += 256) bad |= (pos[2 * i + 1] != 0);
    bad = __syncthreads_or(bad);
    if (tid == 0) g_fmt64 = bad ? 0 : 1;
}

// one CTA per (l, gate, e): write W matrix in fragment order
__global__ void k_wprep(const float* __restrict__ W) {
    extern __shared__ float s[];
    int m = blockIdx.x;                 // m = (l*4 + gate)*9 + e
    int l = m / 36, g = (m / 9) % 4, e = m % 9;
    const float* src = W + (size_t)m * 16384;
    for (int i = threadIdx.x; i < 16384; i += 512) s[i] = src[i];
    __syncthreads();
    uint32_t* dst = g_Wf + (size_t)(l * 9 + e) * 65536 + g * 1024;
    for (int i = threadIdx.x; i < 16384; i += 512) {
        int kc = i >> 12, ks_in = (i >> 10) & 3, nh = (i >> 9) & 1;
        int ntp = (i >> 7) & 3, lane = (i >> 2) & 31, q = i & 3;
        int tig = lane & 3, grp = lane >> 2, ntip = q >> 1, j = q & 1;
        int k = (kc * 4 + ks_in) * 8 + tig + j * 4;
        int n = nh * 64 + (ntp * 2 + ntip) * 8 + grp;
        dst[kc * 16384 + ks_in * 4096 + nh * 512 + ntp * 128 + lane * 4 + q] =
            f2tf(s[k * 128 + n]);
    }
}

__global__ void k_hist(const int* __restrict__ pos) {
    __shared__ int scnt[9], sbase[9];
    int tid = threadIdx.x;
    int t = blockIdx.x * 256 + tid;
    if (tid < 9) scnt[tid] = 0;
    __syncthreads();
    int p = g_fmt64 ? pos[2 * t] : pos[t];
    int e = p > 8 ? 8 : (p < 0 ? 0 : p);
    int my = atomicAdd(&scnt[e], 1);
    __syncthreads();
    if (tid < 9) sbase[tid] = atomicAdd(&g_cnt[tid], scnt[tid]);
    __syncthreads();
    g_tok[e * NTOK + sbase[e] + my] = t;
}

__global__ void k_tiles() {
    __shared__ int ts[10];
    int tid = threadIdx.x;
    if (tid == 0) {
        ts[0] = 0;
        for (int e = 0; e < 9; e++) ts[e + 1] = ts[e] + ((g_cnt[e] + MT - 1) / MT);
        g_ntiles = ts[9];
    }
    __syncthreads();
    int n = ts[9];
    for (int t = tid; t < n; t += blockDim.x) {
        int e = 0;
        while (!(t >= ts[e] && t < ts[e + 1])) e++;
        int s = (t - ts[e]) * MT;
        g_te[t] = e; g_ts[t] = s;
        int rem = g_cnt[e] - s;
        g_tn[t] = rem < MT ? rem : MT;
    }
}

// ---------------- main ----------------
__global__ void __launch_bounds__(512, 1)
k_main(const float* __restrict__ xin, const float* __restrict__ bs, float* __restrict__ out) {
    extern __shared__ __align__(16) char smc[];
    int bid = blockIdx.x;
    if (bid >= g_ntiles) return;
    int e = g_te[bid], s0 = g_ts[bid], nr = g_tn[bid];
    int tid = threadIdx.x, lane = tid & 31, w = tid >> 5;
    int g = w >> 2, mh = (w >> 1) & 1, nh = w & 1;
    int tig = lane & 3, grp = lane >> 2;

    float* Xs = (float*)smc;
    float* P = (float*)(smc + SM_B);
    float* Q = (float*)(smc + SM_B + 65536);
    float* sbias = (float*)(smc + SM_BIAS);
    int* stok = (int*)(smc + SM_TOK);

    if (tid < MT) stok[tid] = (tid < nr) ? g_tok[e * NTOK + s0 + tid] : -1;
    __syncthreads();
    for (int i = tid; i < MT * 128; i += 512) {
        int r = i >> 7, c = i & 127;
        int t = stok[r];
        Xs[r * 132 + c] = (t >= 0) ? xin[(size_t)t * 128 + c] : 0.f;
    }

    const uint4* wsrc0 = (const uint4*)(g_Wf);
    for (int l = 0; l < 2; l++) {
        sbias[tid] = bs[((l * 4 + (tid >> 7)) * 9 + e) * 128 + (tid & 127)];
        const uint4* wsrc = wsrc0 + (size_t)(l * 9 + e) * 16384;

        #define STAGE(kc, buf) do { \
            const uint4* _s = wsrc + (kc) * 4096; \
            uint32_t _d = sptr(smc + SM_B) + (buf) * 65536; \
            _Pragma("unroll") \
            for (int _i = 0; _i < 8; _i++) cpa16(_d + (tid + _i * 512) * 16, _s + tid + _i * 512); \
            asm volatile("cp.async.commit_group;"); \
        } while (0)

        STAGE(0, 0);
        STAGE(1, 1);

        float acc[2][8][4];
        #pragma unroll
        for (int mt = 0; mt < 2; mt++)
            #pragma unroll
            for (int nt = 0; nt < 8; nt++)
                #pragma unroll
                for (int j = 0; j < 4; j++) acc[mt][nt][j] = 0.f;

        for (int kc = 0; kc < 4; kc++) {
            if (kc == 3) asm volatile("cp.async.wait_group 0;");
            else         asm volatile("cp.async.wait_group 1;");
            __syncthreads();
            const char* bsb = smc + SM_B + (kc & 1) * 65536 + g * 4096 + nh * 2048 + lane * 16;
            #pragma unroll
            for (int ks_in = 0; ks_in < 4; ks_in++) {
                int ks = kc * 4 + ks_in;
                uint32_t a[2][4];
                #pragma unroll
                for (int mt = 0; mt < 2; mt++) {
                    const float* xr = Xs + (mh * 32 + mt * 16 + grp) * 132 + ks * 8 + tig;
                    a[mt][0] = f2tf(xr[0]);
                    a[mt][1] = f2tf(xr[8 * 132]);
                    a[mt][2] = f2tf(xr[4]);
                    a[mt][3] = f2tf(xr[8 * 132 + 4]);
                }
                #pragma unroll
                for (int ntp = 0; ntp < 4; ntp++) {
                    uint4 b = *(const uint4*)(bsb + ks_in * 16384 + ntp * 512);
                    mma8(acc[0][2 * ntp],     a[0], b.x, b.y);
                    mma8(acc[1][2 * ntp],     a[1], b.x, b.y);
                    mma8(acc[0][2 * ntp + 1], a[0], b.z, b.w);
                    mma8(acc[1][2 * ntp + 1], a[1], b.z, b.w);
                }
            }
            __syncthreads();
            if (kc < 2) STAGE(kc + 2, kc & 1);
        }
        #undef STAGE

        // epilogue: fragment (r,c) mapping
        #define FRAG_LOOP(BODY) \
            _Pragma("unroll") for (int mt = 0; mt < 2; mt++) \
            _Pragma("unroll") for (int nt = 0; nt < 8; nt++) \
            _Pragma("unroll") for (int j = 0; j < 4; j++) { \
                int r = mh * 32 + mt * 16 + grp + ((j >> 1) << 3); \
                int c = nh * 64 + nt * 8 + tig * 2 + (j & 1); \
                float v = acc[mt][nt][j] + sbias[g * 128 + c]; \
                (void)v; BODY }

        if (g == 0) {
            FRAG_LOOP( P[r * 132 + c] = Xs[r * 132 + c] * sigf(v); )
        } else if (g == 1) {
            FRAG_LOOP( Q[r * 132 + c] = tanhfast(v); )
        }
        __syncthreads();
        if (g == 2) {
            FRAG_LOOP( P[r * 132 + c] += Q[r * 132 + c] * sigf(v); )
        }
        __syncthreads();
        if (g == 3) {
            if (l == 0) {
                FRAG_LOOP( Xs[r * 132 + c] = tanhfast(P[r * 132 + c]) * sigf(v); )
            } else {
                FRAG_LOOP( Q[r * 132 + c] = tanhfast(P[r * 132 + c]) * sigf(v); )
            }
        }
        __syncthreads();
        if (l == 1) {
            for (int i = tid; i < MT * 128; i += 512) {
                int r = i >> 7, c = i & 127;
                int t = stok[r];
                if (t >= 0) out[(size_t)t * 128 + c] = Q[r * 132 + c];
            }
        }
    }
}

extern "C" void kernel_launch(void* const* d_in, const int* in_sizes, int n_in,
                              void* d_out, int out_size) {
    const int* pos = (const int*)d_in[0];
    const float* x = (const float*)d_in[1];
    const float* W = (const float*)d_in[2];
    const float* b = (const float*)d_in[3];
    float* out = (float*)d_out;
    (void)in_sizes; (void)n_in; (void)out_size;
    cudaFuncSetAttribute(k_wprep, cudaFuncAttributeMaxDynamicSharedMemorySize, 65536);
    cudaFuncSetAttribute(k_main, cudaFuncAttributeMaxDynamicSharedMemorySize, SMEM_MAIN);
    k_prep<<<1, 256>>>(pos);
    k_wprep<<<72, 512, 65536>>>(W);
    k_hist<<<256, 256>>>(pos);
    k_tiles<<<1, 1024>>>();
    k_main<<<MAXTILE, 512, SMEM_MAIN>>>(x, b, out);
}

// round 5
// speedup vs baseline: 2.1859x; 1.0802x over previous
#include <cuda_runtime.h>
#include <cuda_fp16.h>
#include <cstdint>

#define NTOK 65536
#define MT 64
#define MAXTILE 1040

// byte offsets in dynamic smem
#define SM_X    0         // 64*68 half2 = 17408 B  (pad 68 pairs/row)
#define SM_B    17408     // 2 x 32768 B double buffer; overlaid by P/Q in epilogue
#define SM_BIAS 84992     // 512 floats
#define SM_TOK  87040     // 64 ints
#define SMEM_MAIN 87296

__device__ int g_cnt[9];
__device__ int g_fmt64;
__device__ int g_ntiles;
__device__ int g_done;
__device__ int g_tok[9 * NTOK];
__device__ int g_te[MAXTILE], g_ts[MAXTILE], g_tn[MAXTILE];
// fragment-ordered fp16 weights: per (l,e): 32768 words (4 gates x 128n x 128k halves)
// word = kc*8192 + ks*4096 + g*1024 + nh*512 + ntp*128 + lane*4 + q
__device__ __align__(16) uint32_t g_Wf[18 * 32768];

__device__ __forceinline__ float ex2f(float x) {
    float r; asm("ex2.approx.f32 %0,%1;" : "=f"(r) : "f"(x)); return r;
}
__device__ __forceinline__ float rcpf(float x) {
    float r; asm("rcp.approx.f32 %0,%1;" : "=f"(r) : "f"(x)); return r;
}
__device__ __forceinline__ float sigf(float v) {
    return rcpf(1.f + ex2f(-1.4426950408889634f * v));
}
__device__ __forceinline__ float tanhfast(float v) {
    return 2.f * rcpf(1.f + ex2f(-2.8853900817779268f * v)) - 1.f;
}
__device__ __forceinline__ void mma16(float* c, const uint32_t* a, uint32_t b0, uint32_t b1) {
    asm volatile(
        "mma.sync.aligned.m16n8k16.row.col.f32.f16.f16.f32 "
        "{%0,%1,%2,%3},{%4,%5,%6,%7},{%8,%9},{%0,%1,%2,%3};"
        : "+f"(c[0]), "+f"(c[1]), "+f"(c[2]), "+f"(c[3])
        : "r"(a[0]), "r"(a[1]), "r"(a[2]), "r"(a[3]), "r"(b0), "r"(b1));
}
__device__ __forceinline__ uint32_t sptr(const void* p) {
    return (uint32_t)__cvta_generic_to_shared(p);
}
__device__ __forceinline__ void cpa16(uint32_t dst, const void* src) {
    asm volatile("cp.async.cg.shared.global [%0],[%1],16;" :: "r"(dst), "l"(src));
}
__device__ __forceinline__ uint32_t packh2(float a, float b) {
    __half2 h = __floats2half2_rn(a, b);
    return *(uint32_t*)&h;
}

// ---------------- prep ----------------
__global__ void k_prep(const int* __restrict__ pos) {
    int tid = threadIdx.x;
    if (tid < 9) g_cnt[tid] = 0;
    if (tid == 9) g_done = 0;
    int bad = 0;
    for (int i = tid; i < 8192; i += 256) bad |= (pos[2 * i + 1] != 0);
    bad = __syncthreads_or(bad);
    if (tid == 0) g_fmt64 = bad ? 0 : 1;
}

// one CTA per (l, gate, e): write W matrix fp16 in fragment order
__global__ void k_wprep(const float* __restrict__ W) {
    extern __shared__ float s[];
    int m = blockIdx.x;                 // m = (l*4 + g)*9 + e
    int l = m / 36, g = (m / 9) % 4, e = m % 9;
    const float* src = W + (size_t)m * 16384;
    for (int i = threadIdx.x; i < 16384; i += 512) s[i] = src[i];
    __syncthreads();
    uint32_t* dst = g_Wf + (size_t)(l * 9 + e) * 32768 + g * 1024;
    for (int i = threadIdx.x; i < 8192; i += 512) {
        int kc = i >> 11, ks = (i >> 10) & 1, nh = (i >> 9) & 1;
        int ntp = (i >> 7) & 3, lane = (i >> 2) & 31, q = i & 3;
        int tig = lane & 3, grp = lane >> 2, ntip = q >> 1, bsel = q & 1;
        int n = nh * 64 + (ntp * 2 + ntip) * 8 + grp;
        int k0 = kc * 32 + ks * 16 + bsel * 8 + 2 * tig;
        dst[kc * 8192 + ks * 4096 + nh * 512 + ntp * 128 + lane * 4 + q] =
            packh2(s[k0 * 128 + n], s[(k0 + 1) * 128 + n]);
    }
}

__global__ void k_hist(const int* __restrict__ pos) {
    __shared__ int scnt[9], sbase[9];
    __shared__ int amlast;
    int tid = threadIdx.x;
    int t = blockIdx.x * 256 + tid;
    if (tid < 9) scnt[tid] = 0;
    __syncthreads();
    int p = g_fmt64 ? pos[2 * t] : pos[t];
    int e = p > 8 ? 8 : (p < 0 ? 0 : p);
    int my = atomicAdd(&scnt[e], 1);
    __syncthreads();
    if (tid < 9) sbase[tid] = atomicAdd(&g_cnt[tid], scnt[tid]);
    __syncthreads();
    g_tok[e * NTOK + sbase[e] + my] = t;
    // last block computes tile descriptors
    __threadfence();
    __syncthreads();
    if (tid == 0) amlast = (atomicAdd(&g_done, 1) == 255);
    __syncthreads();
    if (amlast) {
        __shared__ int ts[10];
        if (tid == 0) {
            ts[0] = 0;
            for (int ee = 0; ee < 9; ee++) ts[ee + 1] = ts[ee] + ((g_cnt[ee] + MT - 1) / MT);
            g_ntiles = ts[9];
        }
        __syncthreads();
        int n = ts[9];
        for (int tt = tid; tt < n; tt += 256) {
            int ee = 0;
            while (!(tt >= ts[ee] && tt < ts[ee + 1])) ee++;
            int s = (tt - ts[ee]) * MT;
            g_te[tt] = ee; g_ts[tt] = s;
            int rem = g_cnt[ee] - s;
            g_tn[tt] = rem < MT ? rem : MT;
        }
    }
}

// ---------------- main ----------------
__global__ void __launch_bounds__(512, 1)
k_main(const float* __restrict__ xin, const float* __restrict__ bs, float* __restrict__ out) {
    extern __shared__ __align__(16) char smc[];
    int bid = blockIdx.x;
    if (bid >= g_ntiles) return;
    int e = g_te[bid], s0 = g_ts[bid], nr = g_tn[bid];
    int tid = threadIdx.x, lane = tid & 31, w = tid >> 5;
    int g = w >> 2, mh = (w >> 1) & 1, nh = w & 1;
    int tig = lane & 3, grp = lane >> 2;

    uint32_t* Xs2 = (uint32_t*)smc;               // half2, stride 68/row
    float* P = (float*)(smc + SM_B);              // 64 x 132 fp32 (epilogue overlay)
    float* Q = P + 64 * 132;
    float* sbias = (float*)(smc + SM_BIAS);
    int* stok = (int*)(smc + SM_TOK);

    if (tid < MT) stok[tid] = (tid < nr) ? g_tok[e * NTOK + s0 + tid] : -1;
    __syncthreads();
    // X -> fp16 smem (float4 gmem loads, half2 stores)
    for (int i = tid; i < MT * 32; i += 512) {
        int r = i >> 5, c4 = i & 31;
        int t = stok[r];
        float4 v = (t >= 0) ? ((const float4*)xin)[(size_t)t * 32 + c4]
                            : make_float4(0.f, 0.f, 0.f, 0.f);
        Xs2[r * 68 + c4 * 2]     = packh2(v.x, v.y);
        Xs2[r * 68 + c4 * 2 + 1] = packh2(v.z, v.w);
    }

    for (int l = 0; l < 2; l++) {
        sbias[tid] = bs[((l * 4 + (tid >> 7)) * 9 + e) * 128 + (tid & 127)];
        const uint4* wsrc = (const uint4*)(g_Wf + (size_t)(l * 9 + e) * 32768);

        #define STAGE(kc, buf) do { \
            const uint4* _s = wsrc + (kc) * 2048; \
            uint32_t _d = sptr(smc + SM_B) + (buf) * 32768; \
            _Pragma("unroll") \
            for (int _i = 0; _i < 4; _i++) cpa16(_d + (tid + _i * 512) * 16, _s + tid + _i * 512); \
            asm volatile("cp.async.commit_group;"); \
        } while (0)

        STAGE(0, 0);
        STAGE(1, 1);

        float acc[2][8][4];
        #pragma unroll
        for (int mt = 0; mt < 2; mt++)
            #pragma unroll
            for (int nt = 0; nt < 8; nt++)
                #pragma unroll
                for (int j = 0; j < 4; j++) acc[mt][nt][j] = 0.f;

        for (int kc = 0; kc < 4; kc++) {
            if (kc == 3) asm volatile("cp.async.wait_group 0;");
            else         asm volatile("cp.async.wait_group 1;");
            __syncthreads();
            const char* bsb = smc + SM_B + (kc & 1) * 32768 + g * 4096 + nh * 2048 + lane * 16;
            #pragma unroll
            for (int ks_in = 0; ks_in < 2; ks_in++) {
                int ks = kc * 2 + ks_in;
                uint32_t a[2][4];
                #pragma unroll
                for (int mt = 0; mt < 2; mt++) {
                    const uint32_t* xr = Xs2 + (mh * 32 + mt * 16 + grp) * 68 + ks * 8 + tig;
                    a[mt][0] = xr[0];
                    a[mt][1] = xr[8 * 68];
                    a[mt][2] = xr[4];
                    a[mt][3] = xr[8 * 68 + 4];
                }
                #pragma unroll
                for (int ntp = 0; ntp < 4; ntp++) {
                    uint4 b = *(const uint4*)(bsb + ks_in * 16384 + ntp * 512);
                    mma16(acc[0][2 * ntp],     a[0], b.x, b.y);
                    mma16(acc[1][2 * ntp],     a[1], b.x, b.y);
                    mma16(acc[0][2 * ntp + 1], a[0], b.z, b.w);
                    mma16(acc[1][2 * ntp + 1], a[1], b.z, b.w);
                }
            }
            __syncthreads();
            if (kc < 2) STAGE(kc + 2, kc & 1);
        }
        #undef STAGE

        #define FRAG_LOOP(BODY) \
            _Pragma("unroll") for (int mt = 0; mt < 2; mt++) \
            _Pragma("unroll") for (int nt = 0; nt < 8; nt++) \
            _Pragma("unroll") for (int j = 0; j < 4; j++) { \
                int r = mh * 32 + mt * 16 + grp + ((j >> 1) << 3); \
                int c = nh * 64 + nt * 8 + tig * 2 + (j & 1); \
                float v = acc[mt][nt][j] + sbias[g * 128 + c]; \
                (void)v; BODY }

        if (g == 0) {
            FRAG_LOOP(
                uint32_t xp = Xs2[r * 68 + (c >> 1)];
                __half2 xh = *(__half2*)&xp;
                float xv = (c & 1) ? __half2float(__high2half(xh)) : __half2float(__low2half(xh));
                P[r * 132 + c] = xv * sigf(v);
            )
        } else if (g == 1) {
            FRAG_LOOP( Q[r * 132 + c] = tanhfast(v); )
        }
        __syncthreads();
        if (g == 2) {
            FRAG_LOOP( P[r * 132 + c] += Q[r * 132 + c] * sigf(v); )
        }
        __syncthreads();
        if (g == 3) {
            FRAG_LOOP( Q[r * 132 + c] = tanhfast(P[r * 132 + c]) * sigf(v); )
        }
        __syncthreads();
        if (l == 0) {
            for (int i = tid; i < MT * 64; i += 512) {
                int r = i >> 6, p = i & 63;
                Xs2[r * 68 + p] = packh2(Q[r * 132 + 2 * p], Q[r * 132 + 2 * p + 1]);
            }
            __syncthreads();
        } else {
            for (int i = tid; i < MT * 32; i += 512) {
                int r = i >> 5, c4 = i & 31;
                int t = stok[r];
                if (t >= 0)
                    ((float4*)out)[(size_t)t * 32 + c4] = *(float4*)&Q[r * 132 + c4 * 4];
            }
        }
    }
}

extern "C" void kernel_launch(void* const* d_in, const int* in_sizes, int n_in,
                              void* d_out, int out_size) {
    const int* pos = (const int*)d_in[0];
    const float* x = (const float*)d_in[1];
    const float* W = (const float*)d_in[2];
    const float* b = (const float*)d_in[3];
    float* out = (float*)d_out;
    (void)in_sizes; (void)n_in; (void)out_size;
    cudaFuncSetAttribute(k_wprep, cudaFuncAttributeMaxDynamicSharedMemorySize, 65536);
    cudaFuncSetAttribute(k_main, cudaFuncAttributeMaxDynamicSharedMemorySize, SMEM_MAIN);
    k_prep<<<1, 256>>>(pos);
    k_wprep<<<72, 512, 65536>>>(W);
    k_hist<<<256, 256>>>(pos);
    k_main<<<MAXTILE, 512, SMEM_MAIN>>>(x, b, out);
}

// round 6
// speedup vs baseline: 3.0642x; 1.4018x over previous
#include <cuda_runtime.h>
#include <cuda_fp16.h>
#include <cstdint>

#define NTOK 65536
#define MT 64
#define MAXTILE 1040

// byte offsets in dynamic smem
#define SM_X    0         // 64*68 half2 = 17408 B (pad 68 words/row)
#define SM_B    17408     // 4 x 32768 B quad buffer
#define SM_PQ   148480    // P: 64x132 f32 (33792 B), Q follows
#define SM_BIAS 216064    // 1024 floats (both layers)
#define SM_TOK  220160    // 64 ints
#define SMEM_MAIN 220416

__device__ int g_cnt[9];
__device__ int g_ntiles;
__device__ int g_done;
__device__ int g_tok[9 * NTOK];
__device__ int g_te[MAXTILE], g_ts[MAXTILE], g_tn[MAXTILE];
// fragment-ordered fp16 weights: per (l,e): 32768 words
// word = kc*8192 + ks*4096 + g*1024 + nh*512 + ntp*128 + lane*4 + q
__device__ __align__(16) uint32_t g_Wf[18 * 32768];

__device__ __forceinline__ float ex2f(float x) {
    float r; asm("ex2.approx.f32 %0,%1;" : "=f"(r) : "f"(x)); return r;
}
__device__ __forceinline__ float rcpf(float x) {
    float r; asm("rcp.approx.f32 %0,%1;" : "=f"(r) : "f"(x)); return r;
}
__device__ __forceinline__ float sigf(float v) {
    return rcpf(1.f + ex2f(-1.4426950408889634f * v));
}
__device__ __forceinline__ float tanhfast(float v) {
    return 2.f * rcpf(1.f + ex2f(-2.8853900817779268f * v)) - 1.f;
}
__device__ __forceinline__ void mma16(float* c, const uint32_t* a, uint32_t b0, uint32_t b1) {
    asm volatile(
        "mma.sync.aligned.m16n8k16.row.col.f32.f16.f16.f32 "
        "{%0,%1,%2,%3},{%4,%5,%6,%7},{%8,%9},{%0,%1,%2,%3};"
        : "+f"(c[0]), "+f"(c[1]), "+f"(c[2]), "+f"(c[3])
        : "r"(a[0]), "r"(a[1]), "r"(a[2]), "r"(a[3]), "r"(b0), "r"(b1));
}
__device__ __forceinline__ uint32_t sptr(const void* p) {
    return (uint32_t)__cvta_generic_to_shared(p);
}
__device__ __forceinline__ void cpa16(uint32_t dst, const void* src) {
    asm volatile("cp.async.cg.shared.global [%0],[%1],16;" :: "r"(dst), "l"(src));
}
__device__ __forceinline__ uint32_t packh2(float a, float b) {
    __half2 h = __floats2half2_rn(a, b);
    return *(uint32_t*)&h;
}

// ---------------- prep ----------------
// one CTA per (l, gate, e): write W matrix fp16 in fragment order.
// Block 0 also zeroes the histogram state for this launch.
__global__ void k_wprep(const float* __restrict__ W) {
    extern __shared__ float s[];
    if (blockIdx.x == 0) {
        if (threadIdx.x < 9) g_cnt[threadIdx.x] = 0;
        if (threadIdx.x == 9) g_done = 0;
    }
    int m = blockIdx.x;                 // m = (l*4 + g)*9 + e
    int l = m / 36, g = (m / 9) % 4, e = m % 9;
    const float* src = W + (size_t)m * 16384;
    for (int i = threadIdx.x; i < 16384; i += 512) s[i] = src[i];
    __syncthreads();
    uint32_t* dst = g_Wf + (size_t)(l * 9 + e) * 32768 + g * 1024;
    for (int i = threadIdx.x; i < 8192; i += 512) {
        int kc = i >> 11, ks = (i >> 10) & 1, nh = (i >> 9) & 1;
        int ntp = (i >> 7) & 3, lane = (i >> 2) & 31, q = i & 3;
        int tig = lane & 3, grp = lane >> 2, bsel = q & 1;
        int n = nh * 64 + (ntp * 2 + (q >> 1)) * 8 + grp;
        int k0 = kc * 32 + ks * 16 + bsel * 8 + 2 * tig;
        dst[kc * 8192 + ks * 4096 + nh * 512 + ntp * 128 + lane * 4 + q] =
            packh2(s[k0 * 128 + n], s[(k0 + 1) * 128 + n]);
    }
}

__global__ void k_hist(const int* __restrict__ pos) {
    __shared__ int scnt[9], sbase[9];
    __shared__ int amlast;
    int tid = threadIdx.x;
    int t = blockIdx.x * 256 + tid;
    if (tid < 9) scnt[tid] = 0;
    // int32-vs-int64 probe (window limited to first 8192 tokens: in-bounds either way)
    int probe = t & 8191;
    int bad = (pos[2 * probe + 1] != 0);
    bad = __syncthreads_or(bad);
    int p = bad ? pos[t] : pos[2 * t];
    int e = p > 8 ? 8 : (p < 0 ? 0 : p);
    int my = atomicAdd(&scnt[e], 1);
    __syncthreads();
    if (tid < 9) sbase[tid] = atomicAdd(&g_cnt[tid], scnt[tid]);
    __syncthreads();
    g_tok[e * NTOK + sbase[e] + my] = t;
    __threadfence();
    __syncthreads();
    if (tid == 0) amlast = (atomicAdd(&g_done, 1) == 255);
    __syncthreads();
    if (amlast) {
        __shared__ int ts[10];
        if (tid == 0) {
            ts[0] = 0;
            for (int ee = 0; ee < 9; ee++) ts[ee + 1] = ts[ee] + ((g_cnt[ee] + MT - 1) / MT);
            g_ntiles = ts[9];
        }
        __syncthreads();
        int n = ts[9];
        for (int tt = tid; tt < n; tt += 256) {
            int ee = 0;
            while (!(tt >= ts[ee] && tt < ts[ee + 1])) ee++;
            int s = (tt - ts[ee]) * MT;
            g_te[tt] = ee; g_ts[tt] = s;
            int rem = g_cnt[ee] - s;
            g_tn[tt] = rem < MT ? rem : MT;
        }
    }
}

// ---------------- main ----------------
__global__ void __launch_bounds__(1024, 1)
k_main(const float* __restrict__ xin, const float* __restrict__ bs, float* __restrict__ out) {
    extern __shared__ __align__(16) char smc[];
    int bid = blockIdx.x;
    if (bid >= g_ntiles) return;
    int e = g_te[bid], s0 = g_ts[bid], nr = g_tn[bid];
    int tid = threadIdx.x, lane = tid & 31, w = tid >> 5;
    int g = w >> 3, mh = (w >> 1) & 3, nh = w & 1;
    int tig = lane & 3, grp = lane >> 2;

    uint32_t* Xs2 = (uint32_t*)smc;               // half2, stride 68 words/row
    float* P = (float*)(smc + SM_PQ);             // 64 x 132 fp32
    float* Q = P + 64 * 132;
    float* sbias = (float*)(smc + SM_BIAS);
    int* stok = (int*)(smc + SM_TOK);

    if (tid < MT) stok[tid] = (tid < nr) ? g_tok[e * NTOK + s0 + tid] : -1;
    sbias[tid] = bs[(((tid >> 9) * 4 + ((tid >> 7) & 3)) * 9 + e) * 128 + (tid & 127)];
    __syncthreads();
    // X -> fp16 smem (float4 gmem loads, half2 stores)
    for (int i = tid; i < MT * 32; i += 1024) {
        int r = i >> 5, c4 = i & 31;
        int t = stok[r];
        float4 v = (t >= 0) ? ((const float4*)xin)[(size_t)t * 32 + c4]
                            : make_float4(0.f, 0.f, 0.f, 0.f);
        Xs2[r * 68 + c4 * 2]     = packh2(v.x, v.y);
        Xs2[r * 68 + c4 * 2 + 1] = packh2(v.z, v.w);
    }

    #define STAGE4(lsel) do { \
        const uint4* _w = (const uint4*)(g_Wf + (size_t)((lsel) * 9 + e) * 32768); \
        uint32_t _d = sptr(smc + SM_B); \
        _Pragma("unroll") \
        for (int _kc = 0; _kc < 4; _kc++) { \
            _Pragma("unroll") \
            for (int _i = 0; _i < 2; _i++) \
                cpa16(_d + _kc * 32768 + (tid + _i * 1024) * 16, \
                      _w + _kc * 2048 + tid + _i * 1024); \
            asm volatile("cp.async.commit_group;"); \
        } \
    } while (0)

    STAGE4(0);

    for (int l = 0; l < 2; l++) {
        float acc[8][4];
        #pragma unroll
        for (int nt = 0; nt < 8; nt++)
            #pragma unroll
            for (int j = 0; j < 4; j++) acc[nt][j] = 0.f;

        #pragma unroll
        for (int kc = 0; kc < 4; kc++) {
            if (kc == 0)      asm volatile("cp.async.wait_group 3;");
            else if (kc == 1) asm volatile("cp.async.wait_group 2;");
            else if (kc == 2) asm volatile("cp.async.wait_group 1;");
            else              asm volatile("cp.async.wait_group 0;");
            __syncthreads();
            const char* bsb = smc + SM_B + kc * 32768 + g * 4096 + nh * 2048 + lane * 16;
            #pragma unroll
            for (int ks_in = 0; ks_in < 2; ks_in++) {
                int ks = kc * 2 + ks_in;
                const uint32_t* xr = Xs2 + (mh * 16 + grp) * 68 + ks * 8 + tig;
                uint32_t a[4];
                a[0] = xr[0]; a[1] = xr[8 * 68]; a[2] = xr[4]; a[3] = xr[8 * 68 + 4];
                #pragma unroll
                for (int ntp = 0; ntp < 4; ntp++) {
                    uint4 b = *(const uint4*)(bsb + ks_in * 16384 + ntp * 512);
                    mma16(acc[2 * ntp],     a, b.x, b.y);
                    mma16(acc[2 * ntp + 1], a, b.z, b.w);
                }
            }
        }
        __syncthreads();             // all warps done reading B buffers
        if (l == 0) STAGE4(1);       // overlap layer-1 W staging with epilogue

        #define FRAG_LOOP(BODY) \
            _Pragma("unroll") for (int nt = 0; nt < 8; nt++) \
            _Pragma("unroll") for (int j = 0; j < 4; j++) { \
                int r = mh * 16 + grp + ((j >> 1) << 3); \
                int c = nh * 64 + nt * 8 + tig * 2 + (j & 1); \
                float v = acc[nt][j] + sbias[l * 512 + g * 128 + c]; \
                (void)v; BODY }

        if (g == 0) {
            FRAG_LOOP(
                uint32_t xp = Xs2[r * 68 + (c >> 1)];
                __half2 xh = *(__half2*)&xp;
                float xv = (c & 1) ? __half2float(__high2half(xh)) : __half2float(__low2half(xh));
                P[r * 132 + c] = xv * sigf(v);
            )
        } else if (g == 1) {
            FRAG_LOOP( Q[r * 132 + c] = tanhfast(v); )
        }
        __syncthreads();
        if (g == 2) {
            FRAG_LOOP( P[r * 132 + c] += Q[r * 132 + c] * sigf(v); )
        }
        __syncthreads();
        if (g == 3) {
            FRAG_LOOP( Q[r * 132 + c] = tanhfast(P[r * 132 + c]) * sigf(v); )
        }
        __syncthreads();
        if (l == 0) {
            for (int i = tid; i < MT * 64; i += 1024) {
                int r = i >> 6, p2 = i & 63;
                Xs2[r * 68 + p2] = packh2(Q[r * 132 + 2 * p2], Q[r * 132 + 2 * p2 + 1]);
            }
            __syncthreads();
        } else {
            for (int i = tid; i < MT * 32; i += 1024) {
                int r = i >> 5, c4 = i & 31;
                int t = stok[r];
                if (t >= 0)
                    ((float4*)out)[(size_t)t * 32 + c4] = *(float4*)&Q[r * 132 + c4 * 4];
            }
        }
    }
    #undef STAGE4
}

extern "C" void kernel_launch(void* const* d_in, const int* in_sizes, int n_in,
                              void* d_out, int out_size) {
    const int* pos = (const int*)d_in[0];
    const float* x = (const float*)d_in[1];
    const float* W = (const float*)d_in[2];
    const float* b = (const float*)d_in[3];
    float* out = (float*)d_out;
    (void)in_sizes; (void)n_in; (void)out_size;
    cudaFuncSetAttribute(k_wprep, cudaFuncAttributeMaxDynamicSharedMemorySize, 65536);
    cudaFuncSetAttribute(k_main, cudaFuncAttributeMaxDynamicSharedMemorySize, SMEM_MAIN);
    k_wprep<<<72, 512, 65536>>>(W);
    k_hist<<<256, 256>>>(pos);
    k_main<<<MAXTILE, 1024, SMEM_MAIN>>>(x, b, out);
}

// round 7
// speedup vs baseline: 4.0083x; 1.3081x over previous
#include <cuda_runtime.h>
#include <cuda_fp16.h>
#include <cstdint>

#define NTOK 65536
#define MT 64
#define MAXTILE 1040

// byte offsets in dynamic smem
#define SM_X    0         // 64*68 half2 = 17408 B (pad 68 words/row)
#define SM_B    17408     // 2 x 65536 B chunk buffers
#define SM_PQ   148480    // P: 64x132 f32 (33792 B), Q follows
#define SM_BIAS 216064    // 1024 floats (both layers)
#define SM_TOK  220160    // 64 ints
#define SMEM_MAIN 220416

__device__ int g_cnt[9];
__device__ int g_ntiles;
__device__ int g_done;
__device__ int g_tok[9 * NTOK];
__device__ int g_te[MAXTILE], g_ts[MAXTILE], g_tn[MAXTILE];
// fragment-ordered fp16 weights: per (l,e): 32768 words
// word = ks*4096 + g*1024 + nh*512 + ntp*128 + lane*4 + q   (ks = 0..7)
__device__ __align__(16) uint32_t g_Wf[18 * 32768];

__device__ __forceinline__ float tanha(float x) {
    float r; asm("tanh.approx.f32 %0,%1;" : "=f"(r) : "f"(x)); return r;
}
__device__ __forceinline__ float sigf(float v) {
    return fmaf(0.5f, tanha(0.5f * v), 0.5f);
}
__device__ __forceinline__ void mma16(float* c, const uint32_t* a, uint32_t b0, uint32_t b1) {
    asm volatile(
        "mma.sync.aligned.m16n8k16.row.col.f32.f16.f16.f32 "
        "{%0,%1,%2,%3},{%4,%5,%6,%7},{%8,%9},{%0,%1,%2,%3};"
        : "+f"(c[0]), "+f"(c[1]), "+f"(c[2]), "+f"(c[3])
        : "r"(a[0]), "r"(a[1]), "r"(a[2]), "r"(a[3]), "r"(b0), "r"(b1));
}
__device__ __forceinline__ uint32_t sptr(const void* p) {
    return (uint32_t)__cvta_generic_to_shared(p);
}
__device__ __forceinline__ void cpa16(uint32_t dst, const void* src) {
    asm volatile("cp.async.cg.shared.global [%0],[%1],16;" :: "r"(dst), "l"(src));
}
__device__ __forceinline__ uint32_t packh2(float a, float b) {
    __half2 h = __floats2half2_rn(a, b);
    return *(uint32_t*)&h;
}

// ---------------- prep ----------------
__global__ void k_wprep(const float* __restrict__ W) {
    extern __shared__ float s[];
    if (blockIdx.x == 0) {
        if (threadIdx.x < 9) g_cnt[threadIdx.x] = 0;
        if (threadIdx.x == 9) g_done = 0;
    }
    int m = blockIdx.x;                 // m = (l*4 + g)*9 + e
    int l = m / 36, g = (m / 9) % 4, e = m % 9;
    const float* src = W + (size_t)m * 16384;
    for (int i = threadIdx.x; i < 16384; i += 512) s[i] = src[i];
    __syncthreads();
    uint32_t* dst = g_Wf + (size_t)(l * 9 + e) * 32768 + g * 1024;
    for (int i = threadIdx.x; i < 8192; i += 512) {
        int ks = i >> 10, nh = (i >> 9) & 1;
        int ntp = (i >> 7) & 3, lane = (i >> 2) & 31, q = i & 3;
        int tig = lane & 3, grp = lane >> 2, bsel = q & 1;
        int n = nh * 64 + (ntp * 2 + (q >> 1)) * 8 + grp;
        int k0 = ks * 16 + bsel * 8 + 2 * tig;
        dst[ks * 4096 + nh * 512 + ntp * 128 + lane * 4 + q] =
            packh2(s[k0 * 128 + n], s[(k0 + 1) * 128 + n]);
    }
}

__global__ void k_hist(const int* __restrict__ pos) {
    __shared__ int scnt[9], sbase[9];
    __shared__ int amlast;
    int tid = threadIdx.x;
    int t = blockIdx.x * 256 + tid;
    if (tid < 9) scnt[tid] = 0;
    int probe = t & 8191;
    int bad = (pos[2 * probe + 1] != 0);
    bad = __syncthreads_or(bad);
    int p = bad ? pos[t] : pos[2 * t];
    int e = p > 8 ? 8 : (p < 0 ? 0 : p);
    int my = atomicAdd(&scnt[e], 1);
    __syncthreads();
    if (tid < 9) sbase[tid] = atomicAdd(&g_cnt[tid], scnt[tid]);
    __syncthreads();
    g_tok[e * NTOK + sbase[e] + my] = t;
    __threadfence();
    __syncthreads();
    if (tid == 0) amlast = (atomicAdd(&g_done, 1) == 255);
    __syncthreads();
    if (amlast) {
        __shared__ int ts[10];
        if (tid == 0) {
            ts[0] = 0;
            for (int ee = 0; ee < 9; ee++) ts[ee + 1] = ts[ee] + ((g_cnt[ee] + MT - 1) / MT);
            g_ntiles = ts[9];
        }
        __syncthreads();
        int n = ts[9];
        for (int tt = tid; tt < n; tt += 256) {
            int ee = 0;
            while (!(tt >= ts[ee] && tt < ts[ee + 1])) ee++;
            int s = (tt - ts[ee]) * MT;
            g_te[tt] = ee; g_ts[tt] = s;
            int rem = g_cnt[ee] - s;
            g_tn[tt] = rem < MT ? rem : MT;
        }
    }
}

// ---------------- main ----------------
__global__ void __launch_bounds__(1024, 1)
k_main(const float* __restrict__ xin, const float* __restrict__ bs, float* __restrict__ out) {
    extern __shared__ __align__(16) char smc[];
    int bid = blockIdx.x;
    if (bid >= g_ntiles) return;
    int e = g_te[bid], s0 = g_ts[bid], nr = g_tn[bid];
    int tid = threadIdx.x, lane = tid & 31, w = tid >> 5;
    int g = w >> 3, mh = (w >> 1) & 3, nh = w & 1;
    int tig = lane & 3, grp = lane >> 2;

    uint32_t* Xs2 = (uint32_t*)smc;               // half2, stride 68 words/row
    float* P = (float*)(smc + SM_PQ);             // 64 x 132 fp32
    float* Q = P + 64 * 132;
    float* sbias = (float*)(smc + SM_BIAS);
    int* stok = (int*)(smc + SM_TOK);

    if (tid < MT) stok[tid] = (tid < nr) ? g_tok[e * NTOK + s0 + tid] : -1;
    sbias[tid] = bs[(((tid >> 9) * 4 + ((tid >> 7) & 3)) * 9 + e) * 128 + (tid & 127)];
    __syncthreads();
    for (int i = tid; i < MT * 32; i += 1024) {
        int r = i >> 5, c4 = i & 31;
        int t = stok[r];
        float4 v = (t >= 0) ? ((const float4*)xin)[(size_t)t * 32 + c4]
                            : make_float4(0.f, 0.f, 0.f, 0.f);
        Xs2[r * 68 + c4 * 2]     = packh2(v.x, v.y);
        Xs2[r * 68 + c4 * 2 + 1] = packh2(v.z, v.w);
    }

    // stage both 64KB chunks of a layer's weights (2 cp.async groups)
    #define STAGE2(lsel) do { \
        const uint4* _w = (const uint4*)(g_Wf + (size_t)((lsel) * 9 + e) * 32768); \
        uint32_t _d = sptr(smc + SM_B); \
        _Pragma("unroll") \
        for (int _ch = 0; _ch < 2; _ch++) { \
            _Pragma("unroll") \
            for (int _i = 0; _i < 4; _i++) \
                cpa16(_d + _ch * 65536 + (tid + _i * 1024) * 16, \
                      _w + _ch * 4096 + tid + _i * 1024); \
            asm volatile("cp.async.commit_group;"); \
        } \
    } while (0)

    STAGE2(0);

    for (int l = 0; l < 2; l++) {
        float acc[8][4];
        #pragma unroll
        for (int nt = 0; nt < 8; nt++)
            #pragma unroll
            for (int j = 0; j < 4; j++) acc[nt][j] = 0.f;

        #pragma unroll
        for (int ch = 0; ch < 2; ch++) {
            if (ch == 0) asm volatile("cp.async.wait_group 1;");
            else         asm volatile("cp.async.wait_group 0;");
            __syncthreads();
            const char* bsb = smc + SM_B + ch * 65536 + g * 4096 + nh * 2048 + lane * 16;
            #pragma unroll
            for (int ksq = 0; ksq < 4; ksq++) {
                int ks = ch * 4 + ksq;
                const uint32_t* xr = Xs2 + (mh * 16 + grp) * 68 + ks * 8 + tig;
                uint32_t a[4];
                a[0] = xr[0]; a[1] = xr[8 * 68]; a[2] = xr[4]; a[3] = xr[8 * 68 + 4];
                #pragma unroll
                for (int ntp = 0; ntp < 4; ntp++) {
                    uint4 b = *(const uint4*)(bsb + ksq * 16384 + ntp * 512);
                    mma16(acc[2 * ntp],     a, b.x, b.y);
                    mma16(acc[2 * ntp + 1], a, b.z, b.w);
                }
            }
        }
        __syncthreads();             // all warps done reading B buffers
        if (l == 0) STAGE2(1);       // overlap layer-1 W staging with epilogue

        #define FRAG_LOOP(BODY) \
            _Pragma("unroll") for (int nt = 0; nt < 8; nt++) \
            _Pragma("unroll") for (int j = 0; j < 4; j++) { \
                int r = mh * 16 + grp + ((j >> 1) << 3); \
                int c = nh * 64 + nt * 8 + tig * 2 + (j & 1); \
                float v = acc[nt][j] + sbias[l * 512 + g * 128 + c]; \
                (void)v; BODY }

        if (g == 0) {
            FRAG_LOOP(
                uint32_t xp = Xs2[r * 68 + (c >> 1)];
                __half2 xh = *(__half2*)&xp;
                float xv = (c & 1) ? __half2float(__high2half(xh)) : __half2float(__low2half(xh));
                P[r * 132 + c] = xv * sigf(v);
            )
        } else if (g == 1) {
            FRAG_LOOP( Q[r * 132 + c] = tanha(v); )
        }
        __syncthreads();
        if (g == 2) {
            FRAG_LOOP( P[r * 132 + c] += Q[r * 132 + c] * sigf(v); )
        }
        __syncthreads();
        if (g == 3) {
            FRAG_LOOP( Q[r * 132 + c] = tanha(P[r * 132 + c]) * sigf(v); )
        }
        __syncthreads();
        if (l == 0) {
            for (int i = tid; i < MT * 64; i += 1024) {
                int r = i >> 6, p2 = i & 63;
                Xs2[r * 68 + p2] = packh2(Q[r * 132 + 2 * p2], Q[r * 132 + 2 * p2 + 1]);
            }
            __syncthreads();
        } else {
            for (int i = tid; i < MT * 32; i += 1024) {
                int r = i >> 5, c4 = i & 31;
                int t = stok[r];
                if (t >= 0)
                    ((float4*)out)[(size_t)t * 32 + c4] = *(float4*)&Q[r * 132 + c4 * 4];
            }
        }
    }
    #undef STAGE2
}

extern "C" void kernel_launch(void* const* d_in, const int* in_sizes, int n_in,
                              void* d_out, int out_size) {
    const int* pos = (const int*)d_in[0];
    const float* x = (const float*)d_in[1];
    const float* W = (const float*)d_in[2];
    const float* b = (const float*)d_in[3];
    float* out = (float*)d_out;
    (void)in_sizes; (void)n_in; (void)out_size;
    cudaFuncSetAttribute(k_wprep, cudaFuncAttributeMaxDynamicSharedMemorySize, 65536);
    cudaFuncSetAttribute(k_main, cudaFuncAttributeMaxDynamicSharedMemorySize, SMEM_MAIN);
    k_wprep<<<72, 512, 65536>>>(W);
    k_hist<<<256, 256>>>(pos);
    k_main<<<MAXTILE, 1024, SMEM_MAIN>>>(x, b, out);
}